// round 10
// baseline (speedup 1.0000x reference)
#include <cuda_runtime.h>

typedef unsigned long long ull;

#define THREADS 256
#define SEQ 512
#define DIN 120
#define NJ 25
#define NC 5
#define ROUTINGS 4
#define WROW 28          // padded W row -> 112B, 16B-aligned const loads
#define CK 20            // k-chunk width
#define NCHK 6           // 120 / 20
#define SSTR 20          // slab row stride (floats) = 80B; phase-conflict-free for LDS.128
#define SLABF (64 * SSTR)   // 1280 floats per buffer

// shared layout (floats): 8 warps x 2 buffers x SLABF, then routing scratch
#define SM_RED  (8 * 2 * SLABF)       // 20480
#define SM_SFIN (SM_RED + 8 * 26)     // 20688
#define SM_TOTF (SM_SFIN + 32)        // 20720 floats = 82880 B

__constant__ float Wc[DIN * WROW];

__device__ __forceinline__ ull ffma2(ull a, ull b, ull c) {
    ull d;
    asm("fma.rn.f32x2 %0, %1, %2, %3;" : "=l"(d) : "l"(a), "l"(b), "l"(c));
    return d;
}
__device__ __forceinline__ ull pack2(float lo, float hi) {
    ull r; asm("mov.b64 %0, {%1, %2};" : "=l"(r) : "f"(lo), "f"(hi)); return r;
}
__device__ __forceinline__ void unpack2(ull v, float& lo, float& hi) {
    asm("mov.b64 {%0, %1}, %2;" : "=f"(lo), "=f"(hi) : "l"(v));
}

// stage one CK-column chunk of this warp's 64 rows into buf (coalesced cp.async)
__device__ __forceinline__ void stage_chunk(const float* __restrict__ xw, int k0,
                                            float* __restrict__ buf, int lane)
{
    #pragma unroll
    for (int m = 0; m < 10; ++m) {
        int idx = lane + 32 * m;          // 0..319 = 64 rows x 5 segs
        int row = idx / 5;
        int seg = idx - row * 5;
        const float* g = xw + row * DIN + k0 + seg * 4;   // 16B-aligned
        unsigned s = (unsigned)__cvta_generic_to_shared(buf + row * SSTR + seg * 4);
        asm volatile("cp.async.cg.shared.global [%0], [%1], 16;" :: "r"(s), "l"(g));
    }
    asm volatile("cp.async.commit_group;");
}

__global__ __launch_bounds__(THREADS, 2)
void caps_kernel(const float* __restrict__ x, float* __restrict__ out)
{
    extern __shared__ float sm[];
    float* red  = sm + SM_RED;
    float* sfin = sm + SM_SFIN;

    const int tid  = threadIdx.x;
    const int wid  = tid >> 5;
    const int lane = tid & 31;
    const int bb   = blockIdx.x;
    const float* xb = x + (size_t)bb * (SEQ * DIN);
    const float* xw = xb + (wid * 64) * DIN;       // warp's 64-row window
    float* slabA = sm + (wid * 2 + 0) * SLABF;
    float* slabB = sm + (wid * 2 + 1) * SLABF;

    // thread owns global rows j0 = wid*64 + lane, j1 = wid*64 + 32 + lane
    ull acc0[13], acc1[13];
    #pragma unroll
    for (int t = 0; t < 13; ++t) { acc0[t] = 0ull; acc1[t] = 0ull; }

    stage_chunk(xw, 0, slabA, lane);

    for (int c = 0; c < NCHK; ++c) {
        float* cur = (c & 1) ? slabB : slabA;
        float* nxt = (c & 1) ? slabA : slabB;
        if (c + 1 < NCHK) {
            stage_chunk(xw, (c + 1) * CK, nxt, lane);
            asm volatile("cp.async.wait_group 1;");   // current chunk complete
        } else {
            asm volatile("cp.async.wait_group 0;");
        }
        __syncwarp();

        // pull this thread's 2 row-chunks into registers (conflict-free LDS.128)
        float4 va4[5], vb4[5];
        const float4* ra = (const float4*)(cur + lane * SSTR);
        const float4* rb = (const float4*)(cur + (lane + 32) * SSTR);
        #pragma unroll
        for (int t = 0; t < 5; ++t) { va4[t] = ra[t]; vb4[t] = rb[t]; }

        const int k0 = c * CK;
        #pragma unroll
        for (int kk = 0; kk < CK; ++kk) {
            float av = ((const float*)va4)[kk];
            float bv = ((const float*)vb4)[kk];
            ull a2 = pack2(av, av);
            ull b2 = pack2(bv, bv);
            const double2* wr = (const double2*)(Wc + (k0 + kk) * WROW);
            #pragma unroll
            for (int t = 0; t < 7; ++t) {
                double2 w = wr[t];                    // constant-port 16B load
                ull wlo = __double_as_longlong(w.x);
                acc0[2 * t] = ffma2(a2, wlo, acc0[2 * t]);
                acc1[2 * t] = ffma2(b2, wlo, acc1[2 * t]);
                if (t < 6) {
                    ull whi = __double_as_longlong(w.y);
                    acc0[2 * t + 1] = ffma2(a2, whi, acc0[2 * t + 1]);
                    acc1[2 * t + 1] = ffma2(b2, whi, acc1[2 * t + 1]);
                }
            }
        }
        __syncwarp();   // all lanes done reading cur before it is re-staged
    }

    // accumulators become routing-resident u_hat rows
    float ua[26], ub[26];
    #pragma unroll
    for (int t = 0; t < 13; ++t) {
        unpack2(acc0[t], ua[2 * t], ua[2 * t + 1]);
        unpack2(acc1[t], ub[2 * t], ub[2 * t + 1]);
    }

    // ================= dynamic routing (4 iterations) =================
    float l0[NC] = {0, 0, 0, 0, 0};
    float l1[NC] = {0, 0, 0, 0, 0};

    for (int it = 0; it < ROUTINGS; ++it) {
        float c0[NC], c1[NC];
        {
            float m0 = l0[0], m1 = l1[0];
            #pragma unroll
            for (int i = 1; i < NC; ++i) { m0 = fmaxf(m0, l0[i]); m1 = fmaxf(m1, l1[i]); }
            float s0 = 0.f, s1 = 0.f;
            #pragma unroll
            for (int i = 0; i < NC; ++i) {
                c0[i] = __expf(l0[i] - m0); s0 += c0[i];
                c1[i] = __expf(l1[i] - m1); s1 += c1[i];
            }
            float r0 = __fdividef(1.f, s0), r1 = __fdividef(1.f, s1);
            #pragma unroll
            for (int i = 0; i < NC; ++i) { c0[i] *= r0; c1[i] *= r1; }
        }

        float part[NJ];
        #pragma unroll
        for (int i = 0; i < NC; ++i)
            #pragma unroll
            for (int k = 0; k < NC; ++k)
                part[i * NC + k] = c0[i] * ua[i * NC + k] + c1[i] * ub[i * NC + k];

        #pragma unroll
        for (int v = 0; v < NJ; ++v) {
            part[v] += __shfl_xor_sync(0xffffffffu, part[v], 16);
            part[v] += __shfl_xor_sync(0xffffffffu, part[v], 8);
            part[v] += __shfl_xor_sync(0xffffffffu, part[v], 4);
            part[v] += __shfl_xor_sync(0xffffffffu, part[v], 2);
            part[v] += __shfl_xor_sync(0xffffffffu, part[v], 1);
        }
        if (lane == 0) {
            #pragma unroll
            for (int v = 0; v < NJ; ++v) red[wid * 26 + v] = part[v];
        }
        __syncthreads();
        if (tid < NJ) {
            float a = 0.f;
            #pragma unroll
            for (int w = 0; w < 8; ++w) a += red[w * 26 + tid];
            sfin[tid] = a;
        }
        __syncthreads();

        float inv[NC];
        #pragma unroll
        for (int i = 0; i < NC; ++i) {
            float n2 = 1e-7f;
            #pragma unroll
            for (int k = 0; k < NC; ++k) {
                float sv = sfin[i * NC + k];
                n2 += sv * sv;
            }
            inv[i] = rsqrtf(n2);
        }

        if (it < ROUTINGS - 1) {
            #pragma unroll
            for (int i = 0; i < NC; ++i) {
                float d0 = 0.f, d1 = 0.f;
                #pragma unroll
                for (int k = 0; k < NC; ++k) {
                    float o = sfin[i * NC + k] * inv[i];
                    d0 += o * ua[i * NC + k];
                    d1 += o * ub[i * NC + k];
                }
                l0[i] = d0; l1[i] = d1;
            }
        } else {
            if (tid < NJ) out[bb * NJ + tid] = sfin[tid] * inv[tid / NC];
        }
    }
}

extern "C" void kernel_launch(void* const* d_in, const int* in_sizes, int n_in,
                              void* d_out, int out_size) {
    const float* x = (const float*)d_in[0];
    const float* W = (const float*)d_in[1];
    float* out = (float*)d_out;
    int batch = in_sizes[0] / (SEQ * DIN);

    // constant W, padded 28-float rows (pad cols stay zero)
    void* wcAddr = nullptr;
    cudaGetSymbolAddress(&wcAddr, Wc);
    cudaMemcpy2DAsync(wcAddr, WROW * sizeof(float),
                      W, NJ * sizeof(float),
                      NJ * sizeof(float), DIN,
                      cudaMemcpyDeviceToDevice);

    cudaFuncSetAttribute(caps_kernel, cudaFuncAttributeMaxDynamicSharedMemorySize,
                         SM_TOTF * (int)sizeof(float));
    caps_kernel<<<batch, THREADS, SM_TOTF * (int)sizeof(float)>>>(x, out);
}